// round 14
// baseline (speedup 1.0000x reference)
#include <cuda_runtime.h>
#include <cuda_bf16.h>
#include <math.h>
#include <stdint.h>

#define NB 4
#define NS 2048
#define NE 1024
#define BSN (NB * NS)

// ---------------- persistent scratch (no cudaMalloc allowed) ----------------
__device__ __nv_bfloat16 g_Xhi[BSN * NE], g_Xlo[BSN * NE];
__device__ __nv_bfloat16 g_Whi[3 * NE * NE], g_Wlo[3 * NE * NE];
__device__ __nv_bfloat16 g_Qhi[BSN * NE], g_Qlo[BSN * NE];
__device__ __nv_bfloat16 g_Khi[BSN * NE], g_Klo[BSN * NE];
__device__ __nv_bfloat16 g_Vthi[(size_t)NE * BSN], g_Vtlo[(size_t)NE * BSN];
__device__ float         g_P[(size_t)NB * NS * NS];
__device__ __nv_bfloat16 g_Phi[(size_t)NB * NS * NS], g_Plo[(size_t)NB * NS * NS];

// ---------------- helpers ----------------
__device__ __forceinline__ uint32_t smem_u32(const void* p) {
    uint32_t a;
    asm("{ .reg .u64 t; cvta.to.shared.u64 t, %1; cvt.u32.u64 %0, t; }" : "=r"(a) : "l"(p));
    return a;
}
__device__ __forceinline__ void ldsm4(uint32_t* r, uint32_t addr) {
    asm volatile("ldmatrix.sync.aligned.m8n8.x4.shared.b16 {%0,%1,%2,%3}, [%4];"
                 : "=r"(r[0]), "=r"(r[1]), "=r"(r[2]), "=r"(r[3]) : "r"(addr));
}
__device__ __forceinline__ void mma16816(float* c, const uint32_t* a, const uint32_t* b) {
    asm volatile("mma.sync.aligned.m16n8k16.row.col.f32.bf16.bf16.f32 "
                 "{%0,%1,%2,%3}, {%4,%5,%6,%7}, {%8,%9}, {%0,%1,%2,%3};"
                 : "+f"(c[0]), "+f"(c[1]), "+f"(c[2]), "+f"(c[3])
                 : "r"(a[0]), "r"(a[1]), "r"(a[2]), "r"(a[3]), "r"(b[0]), "r"(b[1]));
}
__device__ __forceinline__ void cpa16(uint32_t s, const void* g) {
    asm volatile("cp.async.cg.shared.global [%0], [%1], 16;" :: "r"(s), "l"(g));
}
#define CP_COMMIT() asm volatile("cp.async.commit_group;" ::: "memory")
#define CP_WAIT(N)  asm volatile("cp.async.wait_group %0;" :: "n"(N) : "memory")

__device__ __forceinline__ uint32_t pack_bf2(float a, float b) {
    unsigned short ua = __bfloat16_as_ushort(__float2bfloat16(a));
    unsigned short ub = __bfloat16_as_ushort(__float2bfloat16(b));
    return (uint32_t)ua | ((uint32_t)ub << 16);
}
__device__ __forceinline__ void split2(float a, float b, uint32_t& h, uint32_t& l) {
    h = pack_bf2(a, b);
    float ha = __uint_as_float(h << 16);
    float hb = __uint_as_float(h & 0xFFFF0000u);
    l = pack_bf2(a - ha, b - hb);
}

// smem: BK=32 -> unpadded 64 B rows with XOR quad swizzle (q ^= (row>>1)&3).
#define T_A_HI 0
#define T_A_LO 8192
#define T_B_HI 16384
#define T_B_LO 24576
#define STAGE  32768
#define NSTAGE 3
#define SMEM_TOTAL (NSTAGE * STAGE)   // 98304 B per CTA -> 2 CTAs/SM (192 KB)

// ---------------------------------------------------------------------------
// GEMM body: C = alpha*A*B^T (+bias), bf16 hi/lo 3-term split.
// CTA tile 128x128, BK=32, 256 threads (8 warps 2Mx4N), warp tile 64x32.
// 16 warps/SM (2 CTAs). 3-stage cp.async, CP_WAIT(1), staging issued between
// the two kh half-chunks. One __syncthreads per chunk.
// WARP DE-PHASING: odd warps process kh1 first, even warps kh0 first, so at
// any instant half the warps are in LDSM phase and half in MMA phase (breaks
// the barrier-induced MIO/tensor phase alignment).
// biasMode: 0 none, 1 bias[col], 2 bias[row]. OUTMODE: 0 fp32 C, 1 bf16 hi/lo.
// A/B pointers pre-offset to the CTA tile.
// ---------------------------------------------------------------------------
template <int OUTMODE>
__device__ __forceinline__ void gemm_body(
    const __nv_bfloat16* __restrict__ Ahi, const __nv_bfloat16* __restrict__ Alo,
    const __nv_bfloat16* __restrict__ Bhi, const __nv_bfloat16* __restrict__ Blo,
    int lda, int ldb, int Kdim,
    const float* __restrict__ bias, int biasMode,
    float* __restrict__ C, __nv_bfloat16* __restrict__ Chi, __nv_bfloat16* __restrict__ Clo,
    long long cbase, int ldc, int row0, int col0, float alpha)
{
    extern __shared__ char smem[];
    const uint32_t sb = smem_u32(smem);
    const int tid = threadIdx.x;
    const int lane = tid & 31;
    const int wid = tid >> 5;
    const int warpM = (wid & 1) * 64;     // 2 warps in M, 64 rows each
    const int warpN = (wid >> 1) * 32;    // 4 warps in N, 32 cols each
    const int khA = wid & 1;              // de-phasing: this warp's first kh
    const int khB = khA ^ 1;

    float acc[4][4][4];
#pragma unroll
    for (int m = 0; m < 4; m++)
#pragma unroll
        for (int n = 0; n < 4; n++)
#pragma unroll
            for (int q = 0; q < 4; q++) acc[m][n][q] = 0.f;

    // strength-reduced staging state (256 threads: 2 quads per thread per tensor)
    const int r0 = tid >> 2, q0 = tid & 3;
    const uint32_t so0 = (uint32_t)(r0 * 64 + ((q0 ^ ((r0 >> 1) & 3)) * 16));
    const __nv_bfloat16* gAh = Ahi + (long long)r0 * lda + q0 * 8;
    const __nv_bfloat16* gAl = Alo + (long long)r0 * lda + q0 * 8;
    const __nv_bfloat16* gBh = Bhi + (long long)r0 * ldb + q0 * 8;
    const __nv_bfloat16* gBl = Blo + (long long)r0 * ldb + q0 * 8;
    const long long stepA = 64LL * lda;   // rows advance by 64 per p step
    const long long stepB = 64LL * ldb;

    auto issueStage = [&](uint32_t st) {
#pragma unroll
        for (int p = 0; p < 2; p++) {
            const uint32_t so = so0 + (uint32_t)(p * 4096);   // +64 rows * 64 B
            cpa16(st + T_A_HI + so, gAh + p * stepA);
            cpa16(st + T_A_LO + so, gAl + p * stepA);
            cpa16(st + T_B_HI + so, gBh + p * stepB);
            cpa16(st + T_B_LO + so, gBl + p * stepB);
        }
        gAh += 32; gAl += 32; gBh += 32; gBl += 32;
        CP_COMMIT();
    };

    // ldmatrix lane addressing
    const int lr = lane & 15;
    const int lq = lane >> 4;
    const int lsw = (lr >> 1) & 3;
    const uint32_t rowA = (uint32_t)(warpM + lr);
    const uint32_t rowB = (uint32_t)(warpN + lr);

    // one kh half-chunk: 12 LDSM + 48 MMAs
    auto khPart = [&](uint32_t stb, int kh) {
        const uint32_t qb = (uint32_t)(((kh * 2 + lq) ^ lsw) * 16);
        uint32_t ahi[4][4], alo[4][4], bhi[4][2], blo[4][2];
#pragma unroll
        for (int mt = 0; mt < 4; mt++) {
            ldsm4(ahi[mt], stb + T_A_HI + (rowA + mt * 16) * 64 + qb);
            ldsm4(alo[mt], stb + T_A_LO + (rowA + mt * 16) * 64 + qb);
        }
#pragma unroll
        for (int np = 0; np < 2; np++) {
            uint32_t t[4];
            ldsm4(t, stb + T_B_HI + (rowB + np * 16) * 64 + qb);
            bhi[2 * np][0] = t[0]; bhi[2 * np][1] = t[2];
            bhi[2 * np + 1][0] = t[1]; bhi[2 * np + 1][1] = t[3];
            ldsm4(t, stb + T_B_LO + (rowB + np * 16) * 64 + qb);
            blo[2 * np][0] = t[0]; blo[2 * np][1] = t[2];
            blo[2 * np + 1][0] = t[1]; blo[2 * np + 1][1] = t[3];
        }
#pragma unroll
        for (int mt = 0; mt < 4; mt++)
#pragma unroll
            for (int nt = 0; nt < 4; nt++) mma16816(acc[mt][nt], ahi[mt], bhi[nt]);
#pragma unroll
        for (int mt = 0; mt < 4; mt++)
#pragma unroll
            for (int nt = 0; nt < 4; nt++) mma16816(acc[mt][nt], ahi[mt], blo[nt]);
#pragma unroll
        for (int mt = 0; mt < 4; mt++)
#pragma unroll
            for (int nt = 0; nt < 4; nt++) mma16816(acc[mt][nt], alo[mt], bhi[nt]);
    };

    const int CH = Kdim >> 5;      // BK = 32
    const uint32_t sTop = sb + (NSTAGE - 1) * STAGE;
    uint32_t stW = sb, stR = sb;

    issueStage(stW); stW += STAGE;
    issueStage(stW); stW += STAGE;

    for (int c = 0; c < CH; c++) {
        if (c + 1 < CH) { CP_WAIT(1); } else { CP_WAIT(0); }
        __syncthreads();
        khPart(stR, khA);               // half the warps start on kh0, half kh1
        if (c + 2 < CH) {               // staging burst hides under MMA drain
            issueStage(stW);
            stW = (stW == sTop) ? sb : stW + STAGE;
        }
        khPart(stR, khB);
        stR = (stR == sTop) ? sb : stR + STAGE;
        // no tail sync: issue at iter c targets buffer (c-1)%3, which all
        // warps finished computing before this iteration's head sync.
    }

    // ---- epilogue ----
    const int g = lane >> 2, tg = lane & 3;
#pragma unroll
    for (int mt = 0; mt < 4; mt++) {
        const int row = row0 + warpM + mt * 16 + g;
        float rb0 = 0.f, rb8 = 0.f;
        if (biasMode == 2) { rb0 = bias[row]; rb8 = bias[row + 8]; }
#pragma unroll
        for (int nt = 0; nt < 4; nt++) {
            const int col = col0 + warpN + nt * 8 + tg * 2;
            float c0 = acc[mt][nt][0] * alpha;
            float c1 = acc[mt][nt][1] * alpha;
            float c2 = acc[mt][nt][2] * alpha;
            float c3 = acc[mt][nt][3] * alpha;
            if (biasMode == 1) {
                const float b0 = bias[col], b1 = bias[col + 1];
                c0 += b0; c1 += b1; c2 += b0; c3 += b1;
            } else if (biasMode == 2) {
                c0 += rb0; c1 += rb0; c2 += rb8; c3 += rb8;
            }
            const long long i0 = cbase + (long long)row * ldc + col;
            const long long i1 = i0 + (long long)8 * ldc;
            if (OUTMODE == 0) {
                *(float2*)(C + i0) = make_float2(c0, c1);
                *(float2*)(C + i1) = make_float2(c2, c3);
            } else {
                uint32_t h, l;
                split2(c0, c1, h, l);
                *(uint32_t*)(Chi + i0) = h; *(uint32_t*)(Clo + i0) = l;
                split2(c2, c3, h, l);
                *(uint32_t*)(Chi + i1) = h; *(uint32_t*)(Clo + i1) = l;
            }
        }
    }
}

// ---------------------------------------------------------------------------
// Fused projection kernel: z=0 -> K, z=1 -> Q, z=2 -> Vt (remapped tiles).
// grid (8, 64, 3), 256 threads.
// ---------------------------------------------------------------------------
__global__ void __launch_bounds__(256, 2)
gemm_proj3(const __nv_bfloat16* __restrict__ Xhi, const __nv_bfloat16* __restrict__ Xlo,
           const __nv_bfloat16* __restrict__ Whi, const __nv_bfloat16* __restrict__ Wlo,
           const float* __restrict__ bk, const float* __restrict__ bq,
           const float* __restrict__ bv,
           __nv_bfloat16* __restrict__ Khi, __nv_bfloat16* __restrict__ Klo,
           __nv_bfloat16* __restrict__ Qhi, __nv_bfloat16* __restrict__ Qlo,
           __nv_bfloat16* __restrict__ Vthi, __nv_bfloat16* __restrict__ Vtlo)
{
    const int WN = NE * NE;
    const int z = blockIdx.z;
    if (z < 2) {
        // K or Q = X @ W^T + b(col): M = BSN, N = NE
        const int row0 = blockIdx.y * 128;
        const int col0 = blockIdx.x * 128;
        const long long aoff = (long long)row0 * NE;
        const long long boff = (long long)z * WN + (long long)col0 * NE;
        gemm_body<1>(Xhi + aoff, Xlo + aoff, Whi + boff, Wlo + boff,
                     NE, NE, NE,
                     (z == 0) ? bk : bq, 1,
                     nullptr,
                     (z == 0) ? Khi : Qhi, (z == 0) ? Klo : Qlo,
                     0, NE, row0, col0, 1.f);
    } else {
        // Vt = Wv @ X^T + bv(row): M = NE, N = BSN
        const int tx = blockIdx.x + (blockIdx.y & 7) * 8;  // 0..63 (N tiles)
        const int ty = blockIdx.y >> 3;                    // 0..7  (M tiles)
        const int row0 = ty * 128;
        const int col0 = tx * 128;
        const long long aoff = 2LL * WN + (long long)row0 * NE;
        const long long boff = (long long)col0 * NE;
        gemm_body<1>(Whi + aoff, Wlo + aoff, Xhi + boff, Xlo + boff,
                     NE, NE, NE,
                     bv, 2,
                     nullptr, Vthi, Vtlo,
                     0, BSN, row0, col0, 1.f);
    }
}

// ---------------------------------------------------------------------------
// Plain batched NT GEMM wrapper (fp32 out, no bias).
// ---------------------------------------------------------------------------
__global__ void __launch_bounds__(256, 2)
gemm_nt(const __nv_bfloat16* __restrict__ Ahi, const __nv_bfloat16* __restrict__ Alo,
        const __nv_bfloat16* __restrict__ Bhi, const __nv_bfloat16* __restrict__ Blo,
        float* __restrict__ C,
        int lda, int ldb, int ldc, int Kdim,
        long long sA, long long sB, long long sC, float alpha)
{
    const int row0 = blockIdx.y * 128;
    const int col0 = blockIdx.x * 128;
    const long long aoff = (long long)blockIdx.z * sA + (long long)row0 * lda;
    const long long boff = (long long)blockIdx.z * sB + (long long)col0 * ldb;
    gemm_body<0>(Ahi + aoff, Alo + aoff, Bhi + boff, Blo + boff,
                 lda, ldb, Kdim,
                 nullptr, 0,
                 C, nullptr, nullptr,
                 (long long)blockIdx.z * sC, ldc, row0, col0, alpha);
}

// ---------------------------------------------------------------------------
// Fused fp32 -> bf16 hi/lo split over [X | Wk | Wq | Wv] (one launch).
// ---------------------------------------------------------------------------
#define X4  (BSN * NE / 4)
#define W4  (NE * NE / 4)
__global__ __launch_bounds__(256)
void splitAll(const float* __restrict__ X,
              const float* __restrict__ Wk, const float* __restrict__ Wq,
              const float* __restrict__ Wv,
              __nv_bfloat16* __restrict__ Xhi, __nv_bfloat16* __restrict__ Xlo,
              __nv_bfloat16* __restrict__ Whi, __nv_bfloat16* __restrict__ Wlo)
{
    const int i = blockIdx.x * 256 + threadIdx.x;
    const float* src;
    __nv_bfloat16 *hi, *lo;
    int j;
    if (i < X4)                { src = X;  hi = Xhi;          lo = Xlo;          j = i; }
    else if (i < X4 + W4)      { src = Wk; hi = Whi;          lo = Wlo;          j = i - X4; }
    else if (i < X4 + 2 * W4)  { src = Wq; hi = Whi + NE*NE;  lo = Wlo + NE*NE;  j = i - X4 - W4; }
    else                       { src = Wv; hi = Whi + 2*NE*NE; lo = Wlo + 2*NE*NE; j = i - X4 - 2*W4; }
    const float4 v = ((const float4*)src)[j];
    uint32_t h01, l01, h23, l23;
    split2(v.x, v.y, h01, l01);
    split2(v.z, v.w, h23, l23);
    ((uint2*)hi)[j] = make_uint2(h01, h23);
    ((uint2*)lo)[j] = make_uint2(l01, l23);
}

// ---------------------------------------------------------------------------
// Row softmax over 2048, emits bf16 hi/lo. One block (256 thr) per row.
// ---------------------------------------------------------------------------
__global__ __launch_bounds__(256)
void softmax2048(const float* __restrict__ P, __nv_bfloat16* __restrict__ Phi,
                 __nv_bfloat16* __restrict__ Plo)
{
    __shared__ float red[32];
    const float* p = P + (long long)blockIdx.x * NS;
    const int tid = threadIdx.x;

    float v[8];
    {
        const float4 a = *(const float4*)(p + tid * 8);
        const float4 b = *(const float4*)(p + tid * 8 + 4);
        v[0] = a.x; v[1] = a.y; v[2] = a.z; v[3] = a.w;
        v[4] = b.x; v[5] = b.y; v[6] = b.z; v[7] = b.w;
    }

    float m = v[0];
#pragma unroll
    for (int i = 1; i < 8; i++) m = fmaxf(m, v[i]);
#pragma unroll
    for (int o = 16; o > 0; o >>= 1) m = fmaxf(m, __shfl_xor_sync(0xffffffffu, m, o));
    if ((tid & 31) == 0) red[tid >> 5] = m;
    __syncthreads();
    if (tid < 32) {
        float t = (tid < 8) ? red[tid] : -INFINITY;
#pragma unroll
        for (int o = 4; o > 0; o >>= 1) t = fmaxf(t, __shfl_xor_sync(0xffffffffu, t, o));
        if (tid == 0) red[0] = t;
    }
    __syncthreads();
    m = red[0];
    __syncthreads();

    float s = 0.f;
#pragma unroll
    for (int i = 0; i < 8; i++) { v[i] = __expf(v[i] - m); s += v[i]; }
#pragma unroll
    for (int o = 16; o > 0; o >>= 1) s += __shfl_xor_sync(0xffffffffu, s, o);
    if ((tid & 31) == 0) red[tid >> 5] = s;
    __syncthreads();
    if (tid < 32) {
        float t = (tid < 8) ? red[tid] : 0.f;
#pragma unroll
        for (int o = 4; o > 0; o >>= 1) t += __shfl_xor_sync(0xffffffffu, t, o);
        if (tid == 0) red[0] = t;
    }
    __syncthreads();
    const float inv = 1.f / red[0];

    uint4 H, L;
    split2(v[0] * inv, v[1] * inv, H.x, L.x);
    split2(v[2] * inv, v[3] * inv, H.y, L.y);
    split2(v[4] * inv, v[5] * inv, H.z, L.z);
    split2(v[6] * inv, v[7] * inv, H.w, L.w);
    const long long o = (long long)blockIdx.x * NS + tid * 8;
    *(uint4*)(Phi + o) = H;
    *(uint4*)(Plo + o) = L;
}

// ---------------------------------------------------------------------------
// Launcher.
// ---------------------------------------------------------------------------
extern "C" void kernel_launch(void* const* d_in, const int* in_sizes, int n_in,
                              void* d_out, int out_size)
{
    const float* X  = (const float*)d_in[0];
    const float* Wk = (const float*)d_in[1];
    const float* bk = (const float*)d_in[2];
    const float* Wq = (const float*)d_in[3];
    const float* bq = (const float*)d_in[4];
    const float* Wv = (const float*)d_in[5];
    const float* bv = (const float*)d_in[6];
    float* Y = (float*)d_out;

    __nv_bfloat16 *Xhi, *Xlo, *Whi, *Wlo, *Qhi, *Qlo, *Khi, *Klo, *Vthi, *Vtlo, *Phi, *Plo;
    float* Pp;
    cudaGetSymbolAddress((void**)&Xhi, g_Xhi);   cudaGetSymbolAddress((void**)&Xlo, g_Xlo);
    cudaGetSymbolAddress((void**)&Whi, g_Whi);   cudaGetSymbolAddress((void**)&Wlo, g_Wlo);
    cudaGetSymbolAddress((void**)&Qhi, g_Qhi);   cudaGetSymbolAddress((void**)&Qlo, g_Qlo);
    cudaGetSymbolAddress((void**)&Khi, g_Khi);   cudaGetSymbolAddress((void**)&Klo, g_Klo);
    cudaGetSymbolAddress((void**)&Vthi, g_Vthi); cudaGetSymbolAddress((void**)&Vtlo, g_Vtlo);
    cudaGetSymbolAddress((void**)&Phi, g_Phi);   cudaGetSymbolAddress((void**)&Plo, g_Plo);
    cudaGetSymbolAddress((void**)&Pp, g_P);

    cudaFuncSetAttribute(gemm_proj3, cudaFuncAttributeMaxDynamicSharedMemorySize, SMEM_TOTAL);
    cudaFuncSetAttribute(gemm_nt,    cudaFuncAttributeMaxDynamicSharedMemorySize, SMEM_TOTAL);

    const dim3 blk(256);

    // one fused split launch: X, Wk, Wq, Wv
    splitAll<<<(X4 + 3 * W4) / 256, 256>>>(X, Wk, Wq, Wv, Xhi, Xlo, Whi, Wlo);

    // All three projections in ONE launch (z=0 K, z=1 Q, z=2 Vt)
    {
        dim3 grid(NE / 128, BSN / 128, 3);
        gemm_proj3<<<grid, blk, SMEM_TOTAL>>>(
            Xhi, Xlo, Whi, Wlo, bk, bq, bv,
            Khi, Klo, Qhi, Qlo, Vthi, Vtlo);
    }
    // Scores: P[b,j,i] = Q_j . K_i / sqrt(S)  (M=N=2048, batched)
    {
        dim3 grid(NS / 128, NS / 128, NB);
        const float alpha = rsqrtf((float)NS);
        gemm_nt<<<grid, blk, SMEM_TOTAL>>>(
            Qhi, Qlo, Khi, Klo, Pp,
            NE, NE, NS, NE,
            (long long)NS * NE, (long long)NS * NE, (long long)NS * NS, alpha);
    }
    // Softmax over key index i -> bf16 hi/lo
    softmax2048<<<NB * NS, 256>>>(Pp, Phi, Plo);

    // Y = P @ Vt^T  (M=2048, N=1024, K=2048)
    {
        dim3 grid(NE / 128, NS / 128, NB);
        gemm_nt<<<grid, blk, SMEM_TOTAL>>>(
            Phi, Plo, Vthi, Vtlo, Y,
            NS, BSN, NE, NS,
            (long long)NS * NS, (long long)NS, (long long)NS * NE, 1.f);
    }
}

// round 15
// speedup vs baseline: 1.5145x; 1.5145x over previous
#include <cuda_runtime.h>
#include <cuda_fp16.h>
#include <math.h>
#include <stdint.h>

#define NB 4
#define NS 2048
#define NE 1024
#define BSN (NB * NS)

// ---------------- persistent scratch (no cudaMalloc allowed) ----------------
__device__ __half g_Xhi[BSN * NE], g_Xlo[BSN * NE];
__device__ __half g_Whi[3 * NE * NE], g_Wlo[3 * NE * NE];
__device__ __half g_Qhi[BSN * NE], g_Qlo[BSN * NE];
__device__ __half g_Khi[BSN * NE], g_Klo[BSN * NE];
__device__ __half g_Vthi[(size_t)NE * BSN], g_Vtlo[(size_t)NE * BSN];
__device__ float  g_P[(size_t)NB * NS * NS];
__device__ __half g_Phi[(size_t)NB * NS * NS];

// ---------------- helpers ----------------
__device__ __forceinline__ uint32_t smem_u32(const void* p) {
    uint32_t a;
    asm("{ .reg .u64 t; cvta.to.shared.u64 t, %1; cvt.u32.u64 %0, t; }" : "=r"(a) : "l"(p));
    return a;
}
__device__ __forceinline__ void ldsm4(uint32_t* r, uint32_t addr) {
    asm volatile("ldmatrix.sync.aligned.m8n8.x4.shared.b16 {%0,%1,%2,%3}, [%4];"
                 : "=r"(r[0]), "=r"(r[1]), "=r"(r[2]), "=r"(r[3]) : "r"(addr));
}
__device__ __forceinline__ void mma16816(float* c, const uint32_t* a, const uint32_t* b) {
    asm volatile("mma.sync.aligned.m16n8k16.row.col.f32.f16.f16.f32 "
                 "{%0,%1,%2,%3}, {%4,%5,%6,%7}, {%8,%9}, {%0,%1,%2,%3};"
                 : "+f"(c[0]), "+f"(c[1]), "+f"(c[2]), "+f"(c[3])
                 : "r"(a[0]), "r"(a[1]), "r"(a[2]), "r"(a[3]), "r"(b[0]), "r"(b[1]));
}
__device__ __forceinline__ void cpa16(uint32_t s, const void* g) {
    asm volatile("cp.async.cg.shared.global [%0], [%1], 16;" :: "r"(s), "l"(g));
}
#define CP_COMMIT() asm volatile("cp.async.commit_group;" ::: "memory")
#define CP_WAIT(N)  asm volatile("cp.async.wait_group %0;" :: "n"(N) : "memory")

// fp16 hi/lo split of two floats -> packed half2 words
__device__ __forceinline__ void split2h(float a, float b, uint32_t& h, uint32_t& l) {
    const __half ha = __float2half_rn(a), hb = __float2half_rn(b);
    h = (uint32_t)__half_as_ushort(ha) | ((uint32_t)__half_as_ushort(hb) << 16);
    const __half la = __float2half_rn(a - __half2float(ha));
    const __half lb = __float2half_rn(b - __half2float(hb));
    l = (uint32_t)__half_as_ushort(la) | ((uint32_t)__half_as_ushort(lb) << 16);
}

// smem: BK=32 -> unpadded 64 B rows with XOR quad swizzle (q ^= (row>>1)&3).
// fp16 2-term split: A-hi, B-hi, B-lo only (A-lo never loaded).
#define T_A_HI 0
#define T_B_HI 8192
#define T_B_LO 16384
#define STAGE  24576
#define NSTAGE 3
#define SMEM_TOTAL (NSTAGE * STAGE)   // 73728 B per CTA -> 2 CTAs/SM (144 KB)

// ---------------------------------------------------------------------------
// GEMM body: C = alpha*A*B^T (+bias), fp16 2-term split:
//   C ≈ Ahi*Bhi^T + Ahi*Blo^T   (dropped Alo*Bhi ~2^-12 rel, random-sign avg)
// CTA tile 128x128, BK=32, 256 threads (8 warps 2Mx4N), warp tile 64x32.
// 16 warps/SM (2 CTAs). 3-stage cp.async, CP_WAIT(1), mid-chunk staging.
// biasMode: 0 none, 1 bias[col], 2 bias[row]. OUTMODE: 0 fp32 C, 1 fp16 hi/lo.
// A/B pointers pre-offset to the CTA tile.
// ---------------------------------------------------------------------------
template <int OUTMODE>
__device__ __forceinline__ void gemm_body(
    const __half* __restrict__ Ahi,
    const __half* __restrict__ Bhi, const __half* __restrict__ Blo,
    int lda, int ldb, int Kdim,
    const float* __restrict__ bias, int biasMode,
    float* __restrict__ C, __half* __restrict__ Chi, __half* __restrict__ Clo,
    long long cbase, int ldc, int row0, int col0, float alpha)
{
    extern __shared__ char smem[];
    const uint32_t sb = smem_u32(smem);
    const int tid = threadIdx.x;
    const int lane = tid & 31;
    const int wid = tid >> 5;
    const int warpM = (wid & 1) * 64;     // 2 warps in M, 64 rows each
    const int warpN = (wid >> 1) * 32;    // 4 warps in N, 32 cols each
    const int khA = wid & 1;              // warp de-phasing (kept from R14)
    const int khB = khA ^ 1;

    float acc[4][4][4];
#pragma unroll
    for (int m = 0; m < 4; m++)
#pragma unroll
        for (int n = 0; n < 4; n++)
#pragma unroll
            for (int q = 0; q < 4; q++) acc[m][n][q] = 0.f;

    // staging: 256 threads, A-hi 512 quads -> 2/thread; B hi+lo -> 4/thread
    const int r0 = tid >> 2, q0 = tid & 3;
    const uint32_t so0 = (uint32_t)(r0 * 64 + ((q0 ^ ((r0 >> 1) & 3)) * 16));
    const __half* gAh = Ahi + (long long)r0 * lda + q0 * 8;
    const __half* gBh = Bhi + (long long)r0 * ldb + q0 * 8;
    const __half* gBl = Blo + (long long)r0 * ldb + q0 * 8;
    const long long stepA = 64LL * lda;
    const long long stepB = 64LL * ldb;

    auto issueStage = [&](uint32_t st) {
#pragma unroll
        for (int p = 0; p < 2; p++) {
            const uint32_t so = so0 + (uint32_t)(p * 4096);   // +64 rows * 64 B
            cpa16(st + T_A_HI + so, gAh + p * stepA);
            cpa16(st + T_B_HI + so, gBh + p * stepB);
            cpa16(st + T_B_LO + so, gBl + p * stepB);
        }
        gAh += 32; gBh += 32; gBl += 32;
        CP_COMMIT();
    };

    // ldmatrix lane addressing
    const int lr = lane & 15;
    const int lq = lane >> 4;
    const int lsw = (lr >> 1) & 3;
    const uint32_t rowA = (uint32_t)(warpM + lr);
    const uint32_t rowB = (uint32_t)(warpN + lr);

    // one kh half-chunk: 8 LDSM + 32 MMAs
    auto khPart = [&](uint32_t stb, int kh) {
        const uint32_t qb = (uint32_t)(((kh * 2 + lq) ^ lsw) * 16);
        uint32_t ahi[4][4], bhi[4][2], blo[4][2];
#pragma unroll
        for (int mt = 0; mt < 4; mt++)
            ldsm4(ahi[mt], stb + T_A_HI + (rowA + mt * 16) * 64 + qb);
#pragma unroll
        for (int np = 0; np < 2; np++) {
            uint32_t t[4];
            ldsm4(t, stb + T_B_HI + (rowB + np * 16) * 64 + qb);
            bhi[2 * np][0] = t[0]; bhi[2 * np][1] = t[2];
            bhi[2 * np + 1][0] = t[1]; bhi[2 * np + 1][1] = t[3];
            ldsm4(t, stb + T_B_LO + (rowB + np * 16) * 64 + qb);
            blo[2 * np][0] = t[0]; blo[2 * np][1] = t[2];
            blo[2 * np + 1][0] = t[1]; blo[2 * np + 1][1] = t[3];
        }
#pragma unroll
        for (int mt = 0; mt < 4; mt++)
#pragma unroll
            for (int nt = 0; nt < 4; nt++) mma16816(acc[mt][nt], ahi[mt], bhi[nt]);
#pragma unroll
        for (int mt = 0; mt < 4; mt++)
#pragma unroll
            for (int nt = 0; nt < 4; nt++) mma16816(acc[mt][nt], ahi[mt], blo[nt]);
    };

    const int CH = Kdim >> 5;      // BK = 32
    const uint32_t sTop = sb + (NSTAGE - 1) * STAGE;
    uint32_t stW = sb, stR = sb;

    issueStage(stW); stW += STAGE;
    issueStage(stW); stW += STAGE;

    for (int c = 0; c < CH; c++) {
        if (c + 1 < CH) { CP_WAIT(1); } else { CP_WAIT(0); }
        __syncthreads();
        khPart(stR, khA);
        if (c + 2 < CH) {
            issueStage(stW);
            stW = (stW == sTop) ? sb : stW + STAGE;
        }
        khPart(stR, khB);
        stR = (stR == sTop) ? sb : stR + STAGE;
        // no tail sync: issue at iter c targets buffer (c-1)%3, which all
        // warps finished computing before this iteration's head sync.
    }

    // ---- epilogue ----
    const int g = lane >> 2, tg = lane & 3;
#pragma unroll
    for (int mt = 0; mt < 4; mt++) {
        const int row = row0 + warpM + mt * 16 + g;
        float rb0 = 0.f, rb8 = 0.f;
        if (biasMode == 2) { rb0 = bias[row]; rb8 = bias[row + 8]; }
#pragma unroll
        for (int nt = 0; nt < 4; nt++) {
            const int col = col0 + warpN + nt * 8 + tg * 2;
            float c0 = acc[mt][nt][0] * alpha;
            float c1 = acc[mt][nt][1] * alpha;
            float c2 = acc[mt][nt][2] * alpha;
            float c3 = acc[mt][nt][3] * alpha;
            if (biasMode == 1) {
                const float b0 = bias[col], b1 = bias[col + 1];
                c0 += b0; c1 += b1; c2 += b0; c3 += b1;
            } else if (biasMode == 2) {
                c0 += rb0; c1 += rb0; c2 += rb8; c3 += rb8;
            }
            const long long i0 = cbase + (long long)row * ldc + col;
            const long long i1 = i0 + (long long)8 * ldc;
            if (OUTMODE == 0) {
                *(float2*)(C + i0) = make_float2(c0, c1);
                *(float2*)(C + i1) = make_float2(c2, c3);
            } else {
                uint32_t h, l;
                split2h(c0, c1, h, l);
                *(uint32_t*)(Chi + i0) = h; *(uint32_t*)(Clo + i0) = l;
                split2h(c2, c3, h, l);
                *(uint32_t*)(Chi + i1) = h; *(uint32_t*)(Clo + i1) = l;
            }
        }
    }
}

// ---------------------------------------------------------------------------
// Fused projection kernel: z=0 -> K, z=1 -> Q, z=2 -> Vt (remapped tiles).
// grid (8, 64, 3), 256 threads.
// ---------------------------------------------------------------------------
__global__ void __launch_bounds__(256, 2)
gemm_proj3(const __half* __restrict__ Xhi, const __half* __restrict__ Xlo,
           const __half* __restrict__ Whi, const __half* __restrict__ Wlo,
           const float* __restrict__ bk, const float* __restrict__ bq,
           const float* __restrict__ bv,
           __half* __restrict__ Khi, __half* __restrict__ Klo,
           __half* __restrict__ Qhi, __half* __restrict__ Qlo,
           __half* __restrict__ Vthi, __half* __restrict__ Vtlo)
{
    const int WN = NE * NE;
    const int z = blockIdx.z;
    if (z < 2) {
        // K or Q = X @ W^T + b(col): A = X (hi only), B = W (hi+lo)
        const int row0 = blockIdx.y * 128;
        const int col0 = blockIdx.x * 128;
        const long long aoff = (long long)row0 * NE;
        const long long boff = (long long)z * WN + (long long)col0 * NE;
        gemm_body<1>(Xhi + aoff, Whi + boff, Wlo + boff,
                     NE, NE, NE,
                     (z == 0) ? bk : bq, 1,
                     nullptr,
                     (z == 0) ? Khi : Qhi, (z == 0) ? Klo : Qlo,
                     0, NE, row0, col0, 1.f);
    } else {
        // Vt = Wv @ X^T + bv(row): A = Wv (hi only), B = X (hi+lo)
        const int tx = blockIdx.x + (blockIdx.y & 7) * 8;  // 0..63 (N tiles)
        const int ty = blockIdx.y >> 3;                    // 0..7  (M tiles)
        const int row0 = ty * 128;
        const int col0 = tx * 128;
        const long long aoff = 2LL * WN + (long long)row0 * NE;
        const long long boff = (long long)col0 * NE;
        gemm_body<1>(Whi + aoff, Xhi + boff, Xlo + boff,
                     NE, NE, NE,
                     bv, 2,
                     nullptr, Vthi, Vtlo,
                     0, BSN, row0, col0, 1.f);
    }
}

// ---------------------------------------------------------------------------
// Plain batched NT GEMM wrapper (fp32 out, no bias). A hi-only, B hi+lo.
// ---------------------------------------------------------------------------
__global__ void __launch_bounds__(256, 2)
gemm_nt(const __half* __restrict__ Ahi,
        const __half* __restrict__ Bhi, const __half* __restrict__ Blo,
        float* __restrict__ C,
        int lda, int ldb, int ldc, int Kdim,
        long long sA, long long sB, long long sC, float alpha)
{
    const int row0 = blockIdx.y * 128;
    const int col0 = blockIdx.x * 128;
    const long long aoff = (long long)blockIdx.z * sA + (long long)row0 * lda;
    const long long boff = (long long)blockIdx.z * sB + (long long)col0 * ldb;
    gemm_body<0>(Ahi + aoff, Bhi + boff, Blo + boff,
                 lda, ldb, Kdim,
                 nullptr, 0,
                 C, nullptr, nullptr,
                 (long long)blockIdx.z * sC, ldc, row0, col0, alpha);
}

// ---------------------------------------------------------------------------
// Fused fp32 -> fp16 hi/lo split over [X | Wk | Wq | Wv] (one launch).
// ---------------------------------------------------------------------------
#define X4  (BSN * NE / 4)
#define W4  (NE * NE / 4)
__global__ __launch_bounds__(256)
void splitAll(const float* __restrict__ X,
              const float* __restrict__ Wk, const float* __restrict__ Wq,
              const float* __restrict__ Wv,
              __half* __restrict__ Xhi, __half* __restrict__ Xlo,
              __half* __restrict__ Whi, __half* __restrict__ Wlo)
{
    const int i = blockIdx.x * 256 + threadIdx.x;
    const float* src;
    __half *hi, *lo;
    int j;
    if (i < X4)                { src = X;  hi = Xhi;           lo = Xlo;           j = i; }
    else if (i < X4 + W4)      { src = Wk; hi = Whi;           lo = Wlo;           j = i - X4; }
    else if (i < X4 + 2 * W4)  { src = Wq; hi = Whi + NE*NE;   lo = Wlo + NE*NE;   j = i - X4 - W4; }
    else                       { src = Wv; hi = Whi + 2*NE*NE; lo = Wlo + 2*NE*NE; j = i - X4 - 2*W4; }
    const float4 v = ((const float4*)src)[j];
    uint32_t h01, l01, h23, l23;
    split2h(v.x, v.y, h01, l01);
    split2h(v.z, v.w, h23, l23);
    ((uint2*)hi)[j] = make_uint2(h01, h23);
    ((uint2*)lo)[j] = make_uint2(l01, l23);
}

// ---------------------------------------------------------------------------
// Row softmax over 2048, emits fp16 hi ONLY (P is A-operand of Y GEMM; the
// 2-term split never reads A-lo). One block (256 thr) per row.
// ---------------------------------------------------------------------------
__global__ __launch_bounds__(256)
void softmax2048(const float* __restrict__ P, __half* __restrict__ Phi)
{
    __shared__ float red[32];
    const float* p = P + (long long)blockIdx.x * NS;
    const int tid = threadIdx.x;

    float v[8];
    {
        const float4 a = *(const float4*)(p + tid * 8);
        const float4 b = *(const float4*)(p + tid * 8 + 4);
        v[0] = a.x; v[1] = a.y; v[2] = a.z; v[3] = a.w;
        v[4] = b.x; v[5] = b.y; v[6] = b.z; v[7] = b.w;
    }

    float m = v[0];
#pragma unroll
    for (int i = 1; i < 8; i++) m = fmaxf(m, v[i]);
#pragma unroll
    for (int o = 16; o > 0; o >>= 1) m = fmaxf(m, __shfl_xor_sync(0xffffffffu, m, o));
    if ((tid & 31) == 0) red[tid >> 5] = m;
    __syncthreads();
    if (tid < 32) {
        float t = (tid < 8) ? red[tid] : -INFINITY;
#pragma unroll
        for (int o = 4; o > 0; o >>= 1) t = fmaxf(t, __shfl_xor_sync(0xffffffffu, t, o));
        if (tid == 0) red[0] = t;
    }
    __syncthreads();
    m = red[0];
    __syncthreads();

    float s = 0.f;
#pragma unroll
    for (int i = 0; i < 8; i++) { v[i] = __expf(v[i] - m); s += v[i]; }
#pragma unroll
    for (int o = 16; o > 0; o >>= 1) s += __shfl_xor_sync(0xffffffffu, s, o);
    if ((tid & 31) == 0) red[tid >> 5] = s;
    __syncthreads();
    if (tid < 32) {
        float t = (tid < 8) ? red[tid] : 0.f;
#pragma unroll
        for (int o = 4; o > 0; o >>= 1) t += __shfl_xor_sync(0xffffffffu, t, o);
        if (tid == 0) red[0] = t;
    }
    __syncthreads();
    const float inv = 1.f / red[0];

    uint4 H;
    {
        __half h0 = __float2half_rn(v[0] * inv), h1 = __float2half_rn(v[1] * inv);
        __half h2 = __float2half_rn(v[2] * inv), h3 = __float2half_rn(v[3] * inv);
        __half h4 = __float2half_rn(v[4] * inv), h5 = __float2half_rn(v[5] * inv);
        __half h6 = __float2half_rn(v[6] * inv), h7 = __float2half_rn(v[7] * inv);
        H.x = (uint32_t)__half_as_ushort(h0) | ((uint32_t)__half_as_ushort(h1) << 16);
        H.y = (uint32_t)__half_as_ushort(h2) | ((uint32_t)__half_as_ushort(h3) << 16);
        H.z = (uint32_t)__half_as_ushort(h4) | ((uint32_t)__half_as_ushort(h5) << 16);
        H.w = (uint32_t)__half_as_ushort(h6) | ((uint32_t)__half_as_ushort(h7) << 16);
    }
    const long long o = (long long)blockIdx.x * NS + tid * 8;
    *(uint4*)(Phi + o) = H;
}

// ---------------------------------------------------------------------------
// Launcher.
// ---------------------------------------------------------------------------
extern "C" void kernel_launch(void* const* d_in, const int* in_sizes, int n_in,
                              void* d_out, int out_size)
{
    const float* X  = (const float*)d_in[0];
    const float* Wk = (const float*)d_in[1];
    const float* bk = (const float*)d_in[2];
    const float* Wq = (const float*)d_in[3];
    const float* bq = (const float*)d_in[4];
    const float* Wv = (const float*)d_in[5];
    const float* bv = (const float*)d_in[6];
    float* Y = (float*)d_out;

    __half *Xhi, *Xlo, *Whi, *Wlo, *Qhi, *Qlo, *Khi, *Klo, *Vthi, *Vtlo, *Phi;
    float* Pp;
    cudaGetSymbolAddress((void**)&Xhi, g_Xhi);   cudaGetSymbolAddress((void**)&Xlo, g_Xlo);
    cudaGetSymbolAddress((void**)&Whi, g_Whi);   cudaGetSymbolAddress((void**)&Wlo, g_Wlo);
    cudaGetSymbolAddress((void**)&Qhi, g_Qhi);   cudaGetSymbolAddress((void**)&Qlo, g_Qlo);
    cudaGetSymbolAddress((void**)&Khi, g_Khi);   cudaGetSymbolAddress((void**)&Klo, g_Klo);
    cudaGetSymbolAddress((void**)&Vthi, g_Vthi); cudaGetSymbolAddress((void**)&Vtlo, g_Vtlo);
    cudaGetSymbolAddress((void**)&Phi, g_Phi);
    cudaGetSymbolAddress((void**)&Pp, g_P);

    cudaFuncSetAttribute(gemm_proj3, cudaFuncAttributeMaxDynamicSharedMemorySize, SMEM_TOTAL);
    cudaFuncSetAttribute(gemm_nt,    cudaFuncAttributeMaxDynamicSharedMemorySize, SMEM_TOTAL);

    const dim3 blk(256);

    // one fused split launch: X, Wk, Wq, Wv
    splitAll<<<(X4 + 3 * W4) / 256, 256>>>(X, Wk, Wq, Wv, Xhi, Xlo, Whi, Wlo);

    // All three projections in ONE launch (z=0 K, z=1 Q, z=2 Vt)
    {
        dim3 grid(NE / 128, BSN / 128, 3);
        gemm_proj3<<<grid, blk, SMEM_TOTAL>>>(
            Xhi, Xlo, Whi, Wlo, bk, bq, bv,
            Khi, Klo, Qhi, Qlo, Vthi, Vtlo);
    }
    // Scores: P[b,j,i] = Q_j . K_i / sqrt(S)  (A = Q hi, B = K hi+lo)
    {
        dim3 grid(NS / 128, NS / 128, NB);
        const float alpha = rsqrtf((float)NS);
        gemm_nt<<<grid, blk, SMEM_TOTAL>>>(
            Qhi, Khi, Klo, Pp,
            NE, NE, NS, NE,
            (long long)NS * NE, (long long)NS * NE, (long long)NS * NS, alpha);
    }
    // Softmax over key index i -> fp16 hi only
    softmax2048<<<NB * NS, 256>>>(Pp, Phi);

    // Y = P @ Vt^T  (A = P hi, B = Vt hi+lo)
    {
        dim3 grid(NE / 128, NS / 128, NB);
        gemm_nt<<<grid, blk, SMEM_TOTAL>>>(
            Phi, Vthi, Vtlo, Y,
            NS, BSN, NE, NS,
            (long long)NS * NS, (long long)NS, (long long)NS * NE, 1.f);
    }
}

// round 16
// speedup vs baseline: 1.7649x; 1.1653x over previous
#include <cuda_runtime.h>
#include <cuda_fp16.h>
#include <math.h>
#include <stdint.h>

#define NB 4
#define NS 2048
#define NE 1024
#define BSN (NB * NS)

// ---------------- persistent scratch (no cudaMalloc allowed) ----------------
__device__ __half g_Xhi[BSN * NE], g_Xlo[BSN * NE];
__device__ __half g_Whi[3 * NE * NE], g_Wlo[3 * NE * NE];
__device__ __half g_Qhi[BSN * NE];
__device__ __half g_Khi[BSN * NE], g_Klo[BSN * NE];
__device__ __half g_Vthi[(size_t)NE * BSN];
__device__ float  g_P[(size_t)NB * NS * NS];
__device__ __half g_Phi[(size_t)NB * NS * NS];

// ---------------- helpers ----------------
__device__ __forceinline__ uint32_t smem_u32(const void* p) {
    uint32_t a;
    asm("{ .reg .u64 t; cvta.to.shared.u64 t, %1; cvt.u32.u64 %0, t; }" : "=r"(a) : "l"(p));
    return a;
}
__device__ __forceinline__ void ldsm4(uint32_t* r, uint32_t addr) {
    asm volatile("ldmatrix.sync.aligned.m8n8.x4.shared.b16 {%0,%1,%2,%3}, [%4];"
                 : "=r"(r[0]), "=r"(r[1]), "=r"(r[2]), "=r"(r[3]) : "r"(addr));
}
__device__ __forceinline__ void mma16816(float* c, const uint32_t* a, const uint32_t* b) {
    asm volatile("mma.sync.aligned.m16n8k16.row.col.f32.f16.f16.f32 "
                 "{%0,%1,%2,%3}, {%4,%5,%6,%7}, {%8,%9}, {%0,%1,%2,%3};"
                 : "+f"(c[0]), "+f"(c[1]), "+f"(c[2]), "+f"(c[3])
                 : "r"(a[0]), "r"(a[1]), "r"(a[2]), "r"(a[3]), "r"(b[0]), "r"(b[1]));
}
__device__ __forceinline__ void cpa16(uint32_t s, const void* g) {
    asm volatile("cp.async.cg.shared.global [%0], [%1], 16;" :: "r"(s), "l"(g));
}
#define CP_COMMIT() asm volatile("cp.async.commit_group;" ::: "memory")
#define CP_WAIT(N)  asm volatile("cp.async.wait_group %0;" :: "n"(N) : "memory")

// fp16 hi/lo split of two floats -> packed half2 words
__device__ __forceinline__ void split2h(float a, float b, uint32_t& h, uint32_t& l) {
    const __half ha = __float2half_rn(a), hb = __float2half_rn(b);
    h = (uint32_t)__half_as_ushort(ha) | ((uint32_t)__half_as_ushort(hb) << 16);
    const __half la = __float2half_rn(a - __half2float(ha));
    const __half lb = __float2half_rn(b - __half2float(hb));
    l = (uint32_t)__half_as_ushort(la) | ((uint32_t)__half_as_ushort(lb) << 16);
}
__device__ __forceinline__ uint32_t pack2h(float a, float b) {
    return (uint32_t)__half_as_ushort(__float2half_rn(a)) |
           ((uint32_t)__half_as_ushort(__float2half_rn(b)) << 16);
}

// smem: BK=32 -> unpadded 64 B rows with XOR quad swizzle (q ^= (row>>1)&3).
#define T_A_HI 0
#define T_B_HI 8192
#define T_B_LO 16384
#define STAGE  24576
#define NSTAGE 3
#define SMEM_TOTAL (NSTAGE * STAGE)   // 73728 B per CTA -> 2 CTAs/SM (144 KB)

// ---------------------------------------------------------------------------
// GEMM body: C = alpha*A*B^T (+bias), fp16 split.
//   TERMS=2: C ≈ Ahi*Bhi^T + Ahi*Blo^T   (~2^-12 avg dropped-term error)
//   TERMS=1: C ≈ Ahi*Bhi^T               (pure fp16; linear-path only)
// CTA tile 128x128, BK=32, 256 threads (8 warps 2Mx4N), warp tile 64x32.
// 16 warps/SM (2 CTAs). 3-stage cp.async, CP_WAIT(1), mid-chunk staging,
// warp de-phasing. biasMode: 0 none, 1 col, 2 row.
// OUTMODE: 0 fp32 C, 1 fp16 hi (+lo when loOut).
// ---------------------------------------------------------------------------
template <int OUTMODE, int TERMS>
__device__ __forceinline__ void gemm_body(
    const __half* __restrict__ Ahi,
    const __half* __restrict__ Bhi, const __half* __restrict__ Blo,
    int lda, int ldb, int Kdim,
    const float* __restrict__ bias, int biasMode,
    float* __restrict__ C, __half* __restrict__ Chi, __half* __restrict__ Clo,
    int loOut,
    long long cbase, int ldc, int row0, int col0, float alpha)
{
    extern __shared__ char smem[];
    const uint32_t sb = smem_u32(smem);
    const int tid = threadIdx.x;
    const int lane = tid & 31;
    const int wid = tid >> 5;
    const int warpM = (wid & 1) * 64;
    const int warpN = (wid >> 1) * 32;
    const int khA = wid & 1;
    const int khB = khA ^ 1;

    float acc[4][4][4];
#pragma unroll
    for (int m = 0; m < 4; m++)
#pragma unroll
        for (int n = 0; n < 4; n++)
#pragma unroll
            for (int q = 0; q < 4; q++) acc[m][n][q] = 0.f;

    const int r0 = tid >> 2, q0 = tid & 3;
    const uint32_t so0 = (uint32_t)(r0 * 64 + ((q0 ^ ((r0 >> 1) & 3)) * 16));
    const __half* gAh = Ahi + (long long)r0 * lda + q0 * 8;
    const __half* gBh = Bhi + (long long)r0 * ldb + q0 * 8;
    const __half* gBl = (TERMS == 2) ? (Blo + (long long)r0 * ldb + q0 * 8) : nullptr;
    const long long stepA = 64LL * lda;
    const long long stepB = 64LL * ldb;

    auto issueStage = [&](uint32_t st) {
#pragma unroll
        for (int p = 0; p < 2; p++) {
            const uint32_t so = so0 + (uint32_t)(p * 4096);
            cpa16(st + T_A_HI + so, gAh + p * stepA);
            cpa16(st + T_B_HI + so, gBh + p * stepB);
            if (TERMS == 2) cpa16(st + T_B_LO + so, gBl + p * stepB);
        }
        gAh += 32; gBh += 32;
        if (TERMS == 2) gBl += 32;
        CP_COMMIT();
    };

    const int lr = lane & 15;
    const int lq = lane >> 4;
    const int lsw = (lr >> 1) & 3;
    const uint32_t rowA = (uint32_t)(warpM + lr);
    const uint32_t rowB = (uint32_t)(warpN + lr);

    auto khPart = [&](uint32_t stb, int kh) {
        const uint32_t qb = (uint32_t)(((kh * 2 + lq) ^ lsw) * 16);
        uint32_t ahi[4][4], bhi[4][2], blo[4][2];
#pragma unroll
        for (int mt = 0; mt < 4; mt++)
            ldsm4(ahi[mt], stb + T_A_HI + (rowA + mt * 16) * 64 + qb);
#pragma unroll
        for (int np = 0; np < 2; np++) {
            uint32_t t[4];
            ldsm4(t, stb + T_B_HI + (rowB + np * 16) * 64 + qb);
            bhi[2 * np][0] = t[0]; bhi[2 * np][1] = t[2];
            bhi[2 * np + 1][0] = t[1]; bhi[2 * np + 1][1] = t[3];
            if (TERMS == 2) {
                ldsm4(t, stb + T_B_LO + (rowB + np * 16) * 64 + qb);
                blo[2 * np][0] = t[0]; blo[2 * np][1] = t[2];
                blo[2 * np + 1][0] = t[1]; blo[2 * np + 1][1] = t[3];
            }
        }
#pragma unroll
        for (int mt = 0; mt < 4; mt++)
#pragma unroll
            for (int nt = 0; nt < 4; nt++) mma16816(acc[mt][nt], ahi[mt], bhi[nt]);
        if (TERMS == 2) {
#pragma unroll
            for (int mt = 0; mt < 4; mt++)
#pragma unroll
                for (int nt = 0; nt < 4; nt++) mma16816(acc[mt][nt], ahi[mt], blo[nt]);
        }
    };

    const int CH = Kdim >> 5;      // BK = 32
    const uint32_t sTop = sb + (NSTAGE - 1) * STAGE;
    uint32_t stW = sb, stR = sb;

    issueStage(stW); stW += STAGE;
    issueStage(stW); stW += STAGE;

    for (int c = 0; c < CH; c++) {
        if (c + 1 < CH) { CP_WAIT(1); } else { CP_WAIT(0); }
        __syncthreads();
        khPart(stR, khA);
        if (c + 2 < CH) {
            issueStage(stW);
            stW = (stW == sTop) ? sb : stW + STAGE;
        }
        khPart(stR, khB);
        stR = (stR == sTop) ? sb : stR + STAGE;
        // no tail sync: issue at iter c targets buffer (c-1)%3, which all
        // warps finished computing before this iteration's head sync.
    }

    // ---- epilogue ----
    const int g = lane >> 2, tg = lane & 3;
#pragma unroll
    for (int mt = 0; mt < 4; mt++) {
        const int row = row0 + warpM + mt * 16 + g;
        float rb0 = 0.f, rb8 = 0.f;
        if (biasMode == 2) { rb0 = bias[row]; rb8 = bias[row + 8]; }
#pragma unroll
        for (int nt = 0; nt < 4; nt++) {
            const int col = col0 + warpN + nt * 8 + tg * 2;
            float c0 = acc[mt][nt][0] * alpha;
            float c1 = acc[mt][nt][1] * alpha;
            float c2 = acc[mt][nt][2] * alpha;
            float c3 = acc[mt][nt][3] * alpha;
            if (biasMode == 1) {
                const float b0 = bias[col], b1 = bias[col + 1];
                c0 += b0; c1 += b1; c2 += b0; c3 += b1;
            } else if (biasMode == 2) {
                c0 += rb0; c1 += rb0; c2 += rb8; c3 += rb8;
            }
            const long long i0 = cbase + (long long)row * ldc + col;
            const long long i1 = i0 + (long long)8 * ldc;
            if (OUTMODE == 0) {
                *(float2*)(C + i0) = make_float2(c0, c1);
                *(float2*)(C + i1) = make_float2(c2, c3);
            } else {
                if (loOut) {
                    uint32_t h, l;
                    split2h(c0, c1, h, l);
                    *(uint32_t*)(Chi + i0) = h; *(uint32_t*)(Clo + i0) = l;
                    split2h(c2, c3, h, l);
                    *(uint32_t*)(Chi + i1) = h; *(uint32_t*)(Clo + i1) = l;
                } else {
                    *(uint32_t*)(Chi + i0) = pack2h(c0, c1);
                    *(uint32_t*)(Chi + i1) = pack2h(c2, c3);
                }
            }
        }
    }
}

// ---------------------------------------------------------------------------
// Fused projection kernel: z=0 -> K (hi+lo), z=1 -> Q (hi only),
// z=2 -> Vt (hi only, remapped tiles). grid (8, 64, 3), 256 threads.
// ---------------------------------------------------------------------------
__global__ void __launch_bounds__(256, 2)
gemm_proj3(const __half* __restrict__ Xhi, const __half* __restrict__ Xlo,
           const __half* __restrict__ Whi, const __half* __restrict__ Wlo,
           const float* __restrict__ bk, const float* __restrict__ bq,
           const float* __restrict__ bv,
           __half* __restrict__ Khi, __half* __restrict__ Klo,
           __half* __restrict__ Qhi,
           __half* __restrict__ Vthi)
{
    const int WN = NE * NE;
    const int z = blockIdx.z;
    if (z < 2) {
        // K or Q = X @ W^T + b(col): A = X (hi only), B = W (hi+lo)
        const int row0 = blockIdx.y * 128;
        const int col0 = blockIdx.x * 128;
        const long long aoff = (long long)row0 * NE;
        const long long boff = (long long)z * WN + (long long)col0 * NE;
        gemm_body<1, 2>(Xhi + aoff, Whi + boff, Wlo + boff,
                        NE, NE, NE,
                        (z == 0) ? bk : bq, 1,
                        nullptr,
                        (z == 0) ? Khi : Qhi, (z == 0) ? Klo : nullptr,
                        (z == 0) ? 1 : 0,
                        0, NE, row0, col0, 1.f);
    } else {
        // Vt = Wv @ X^T + bv(row): A = Wv (hi only), B = X (hi+lo), hi out only
        const int tx = blockIdx.x + (blockIdx.y & 7) * 8;  // 0..63 (N tiles)
        const int ty = blockIdx.y >> 3;                    // 0..7  (M tiles)
        const int row0 = ty * 128;
        const int col0 = tx * 128;
        const long long aoff = 2LL * WN + (long long)row0 * NE;
        const long long boff = (long long)col0 * NE;
        gemm_body<1, 2>(Whi + aoff, Xhi + boff, Xlo + boff,
                        NE, NE, NE,
                        bv, 2,
                        nullptr, Vthi, nullptr, 0,
                        0, BSN, row0, col0, 1.f);
    }
}

// ---------------------------------------------------------------------------
// Plain batched NT GEMM wrapper (fp32 out, no bias). TERMS = 1 or 2.
// ---------------------------------------------------------------------------
template <int TERMS>
__global__ void __launch_bounds__(256, 2)
gemm_nt(const __half* __restrict__ Ahi,
        const __half* __restrict__ Bhi, const __half* __restrict__ Blo,
        float* __restrict__ C,
        int lda, int ldb, int ldc, int Kdim,
        long long sA, long long sB, long long sC, float alpha)
{
    const int row0 = blockIdx.y * 128;
    const int col0 = blockIdx.x * 128;
    const long long aoff = (long long)blockIdx.z * sA + (long long)row0 * lda;
    const long long boff = (long long)blockIdx.z * sB + (long long)col0 * ldb;
    gemm_body<0, TERMS>(Ahi + aoff, Bhi + boff, (TERMS == 2) ? (Blo + boff) : nullptr,
                        lda, ldb, Kdim,
                        nullptr, 0,
                        C, nullptr, nullptr, 0,
                        (long long)blockIdx.z * sC, ldc, row0, col0, alpha);
}

// ---------------------------------------------------------------------------
// Fused fp32 -> fp16 hi/lo split over [X | Wk | Wq | Wv] (one launch).
// ---------------------------------------------------------------------------
#define X4  (BSN * NE / 4)
#define W4  (NE * NE / 4)
__global__ __launch_bounds__(256)
void splitAll(const float* __restrict__ X,
              const float* __restrict__ Wk, const float* __restrict__ Wq,
              const float* __restrict__ Wv,
              __half* __restrict__ Xhi, __half* __restrict__ Xlo,
              __half* __restrict__ Whi, __half* __restrict__ Wlo)
{
    const int i = blockIdx.x * 256 + threadIdx.x;
    const float* src;
    __half *hi, *lo;
    int j;
    if (i < X4)                { src = X;  hi = Xhi;           lo = Xlo;           j = i; }
    else if (i < X4 + W4)      { src = Wk; hi = Whi;           lo = Wlo;           j = i - X4; }
    else if (i < X4 + 2 * W4)  { src = Wq; hi = Whi + NE*NE;   lo = Wlo + NE*NE;   j = i - X4 - W4; }
    else                       { src = Wv; hi = Whi + 2*NE*NE; lo = Wlo + 2*NE*NE; j = i - X4 - 2*W4; }
    const float4 v = ((const float4*)src)[j];
    uint32_t h01, l01, h23, l23;
    split2h(v.x, v.y, h01, l01);
    split2h(v.z, v.w, h23, l23);
    ((uint2*)hi)[j] = make_uint2(h01, h23);
    ((uint2*)lo)[j] = make_uint2(l01, l23);
}

// ---------------------------------------------------------------------------
// Row softmax over 2048, emits fp16 hi only. One block (256 thr) per row.
// ---------------------------------------------------------------------------
__global__ __launch_bounds__(256)
void softmax2048(const float* __restrict__ P, __half* __restrict__ Phi)
{
    __shared__ float red[32];
    const float* p = P + (long long)blockIdx.x * NS;
    const int tid = threadIdx.x;

    float v[8];
    {
        const float4 a = *(const float4*)(p + tid * 8);
        const float4 b = *(const float4*)(p + tid * 8 + 4);
        v[0] = a.x; v[1] = a.y; v[2] = a.z; v[3] = a.w;
        v[4] = b.x; v[5] = b.y; v[6] = b.z; v[7] = b.w;
    }

    float m = v[0];
#pragma unroll
    for (int i = 1; i < 8; i++) m = fmaxf(m, v[i]);
#pragma unroll
    for (int o = 16; o > 0; o >>= 1) m = fmaxf(m, __shfl_xor_sync(0xffffffffu, m, o));
    if ((tid & 31) == 0) red[tid >> 5] = m;
    __syncthreads();
    if (tid < 32) {
        float t = (tid < 8) ? red[tid] : -INFINITY;
#pragma unroll
        for (int o = 4; o > 0; o >>= 1) t = fmaxf(t, __shfl_xor_sync(0xffffffffu, t, o));
        if (tid == 0) red[0] = t;
    }
    __syncthreads();
    m = red[0];
    __syncthreads();

    float s = 0.f;
#pragma unroll
    for (int i = 0; i < 8; i++) { v[i] = __expf(v[i] - m); s += v[i]; }
#pragma unroll
    for (int o = 16; o > 0; o >>= 1) s += __shfl_xor_sync(0xffffffffu, s, o);
    if ((tid & 31) == 0) red[tid >> 5] = s;
    __syncthreads();
    if (tid < 32) {
        float t = (tid < 8) ? red[tid] : 0.f;
#pragma unroll
        for (int o = 4; o > 0; o >>= 1) t += __shfl_xor_sync(0xffffffffu, t, o);
        if (tid == 0) red[0] = t;
    }
    __syncthreads();
    const float inv = 1.f / red[0];

    uint4 H;
    H.x = pack2h(v[0] * inv, v[1] * inv);
    H.y = pack2h(v[2] * inv, v[3] * inv);
    H.z = pack2h(v[4] * inv, v[5] * inv);
    H.w = pack2h(v[6] * inv, v[7] * inv);
    const long long o = (long long)blockIdx.x * NS + tid * 8;
    *(uint4*)(Phi + o) = H;
}

// ---------------------------------------------------------------------------
// Launcher.
// ---------------------------------------------------------------------------
extern "C" void kernel_launch(void* const* d_in, const int* in_sizes, int n_in,
                              void* d_out, int out_size)
{
    const float* X  = (const float*)d_in[0];
    const float* Wk = (const float*)d_in[1];
    const float* bk = (const float*)d_in[2];
    const float* Wq = (const float*)d_in[3];
    const float* bq = (const float*)d_in[4];
    const float* Wv = (const float*)d_in[5];
    const float* bv = (const float*)d_in[6];
    float* Y = (float*)d_out;

    __half *Xhi, *Xlo, *Whi, *Wlo, *Qhi, *Khi, *Klo, *Vthi, *Phi;
    float* Pp;
    cudaGetSymbolAddress((void**)&Xhi, g_Xhi);   cudaGetSymbolAddress((void**)&Xlo, g_Xlo);
    cudaGetSymbolAddress((void**)&Whi, g_Whi);   cudaGetSymbolAddress((void**)&Wlo, g_Wlo);
    cudaGetSymbolAddress((void**)&Qhi, g_Qhi);
    cudaGetSymbolAddress((void**)&Khi, g_Khi);   cudaGetSymbolAddress((void**)&Klo, g_Klo);
    cudaGetSymbolAddress((void**)&Vthi, g_Vthi);
    cudaGetSymbolAddress((void**)&Phi, g_Phi);
    cudaGetSymbolAddress((void**)&Pp, g_P);

    cudaFuncSetAttribute(gemm_proj3, cudaFuncAttributeMaxDynamicSharedMemorySize, SMEM_TOTAL);
    cudaFuncSetAttribute(gemm_nt<2>, cudaFuncAttributeMaxDynamicSharedMemorySize, SMEM_TOTAL);
    cudaFuncSetAttribute(gemm_nt<1>, cudaFuncAttributeMaxDynamicSharedMemorySize, SMEM_TOTAL);

    const dim3 blk(256);

    // one fused split launch: X, Wk, Wq, Wv
    splitAll<<<(X4 + 3 * W4) / 256, 256>>>(X, Wk, Wq, Wv, Xhi, Xlo, Whi, Wlo);

    // All three projections in ONE launch (z=0 K hi+lo, z=1 Q hi, z=2 Vt hi)
    {
        dim3 grid(NE / 128, BSN / 128, 3);
        gemm_proj3<<<grid, blk, SMEM_TOTAL>>>(
            Xhi, Xlo, Whi, Wlo, bk, bq, bv,
            Khi, Klo, Qhi, Vthi);
    }
    // Scores: P[b,j,i] = Q_j . K_i / sqrt(S)  (A = Q hi, B = K hi+lo)
    {
        dim3 grid(NS / 128, NS / 128, NB);
        const float alpha = rsqrtf((float)NS);
        gemm_nt<2><<<grid, blk, SMEM_TOTAL>>>(
            Qhi, Khi, Klo, Pp,
            NE, NE, NS, NE,
            (long long)NS * NE, (long long)NS * NE, (long long)NS * NS, alpha);
    }
    // Softmax over key index i -> fp16 hi only
    softmax2048<<<NB * NS, 256>>>(Pp, Phi);

    // Y = P @ Vt^T  (A = P hi, B = Vt hi; pure fp16 single term — linear path)
    {
        dim3 grid(NE / 128, NS / 128, NB);
        gemm_nt<1><<<grid, blk, SMEM_TOTAL>>>(
            Phi, Vthi, nullptr, Y,
            NS, BSN, NE, NS,
            (long long)NS * NS, (long long)NS, (long long)NS * NE, 1.f);
    }
}

// round 17
// speedup vs baseline: 2.6518x; 1.5025x over previous
#include <cuda_runtime.h>
#include <cuda_fp16.h>
#include <math.h>
#include <stdint.h>

#define NB 4
#define NS 2048
#define NE 1024
#define BSN (NB * NS)

// ---------------- persistent scratch (no cudaMalloc allowed) ----------------
__device__ __half g_Xh[BSN * NE];
__device__ __half g_Wh[3 * NE * NE];
__device__ __half g_Qh[BSN * NE];
__device__ __half g_Kh[BSN * NE];
__device__ __half g_Vth[(size_t)NE * BSN];
__device__ float  g_P[(size_t)NB * NS * NS];
__device__ __half g_Ph[(size_t)NB * NS * NS];

// ---------------- helpers ----------------
__device__ __forceinline__ uint32_t smem_u32(const void* p) {
    uint32_t a;
    asm("{ .reg .u64 t; cvta.to.shared.u64 t, %1; cvt.u32.u64 %0, t; }" : "=r"(a) : "l"(p));
    return a;
}
__device__ __forceinline__ void ldsm4(uint32_t* r, uint32_t addr) {
    asm volatile("ldmatrix.sync.aligned.m8n8.x4.shared.b16 {%0,%1,%2,%3}, [%4];"
                 : "=r"(r[0]), "=r"(r[1]), "=r"(r[2]), "=r"(r[3]) : "r"(addr));
}
__device__ __forceinline__ void mma16816(float* c, const uint32_t* a, const uint32_t* b) {
    asm volatile("mma.sync.aligned.m16n8k16.row.col.f32.f16.f16.f32 "
                 "{%0,%1,%2,%3}, {%4,%5,%6,%7}, {%8,%9}, {%0,%1,%2,%3};"
                 : "+f"(c[0]), "+f"(c[1]), "+f"(c[2]), "+f"(c[3])
                 : "r"(a[0]), "r"(a[1]), "r"(a[2]), "r"(a[3]), "r"(b[0]), "r"(b[1]));
}
__device__ __forceinline__ void cpa16(uint32_t s, const void* g) {
    asm volatile("cp.async.cg.shared.global [%0], [%1], 16;" :: "r"(s), "l"(g));
}
#define CP_COMMIT() asm volatile("cp.async.commit_group;" ::: "memory")
#define CP_WAIT(N)  asm volatile("cp.async.wait_group %0;" :: "n"(N) : "memory")

__device__ __forceinline__ uint32_t pack2h(float a, float b) {
    return (uint32_t)__half_as_ushort(__float2half_rn(a)) |
           ((uint32_t)__half_as_ushort(__float2half_rn(b)) << 16);
}

// smem: BK=32 -> unpadded 64 B rows with XOR quad swizzle (q ^= (row>>1)&3).
// Pure fp16 single-term: A and B tiles only.
#define T_A 0
#define T_B 8192
#define STAGE  16384
#define NSTAGE 3
#define SMEM_TOTAL (NSTAGE * STAGE)   // 49152 B per CTA -> 2 CTAs/SM

// ---------------------------------------------------------------------------
// GEMM body: C = alpha*A*B^T (+bias), pure fp16 operands, fp32 accum.
// CTA tile 128x128, BK=32, 256 threads (8 warps 2Mx4N), warp tile 64x32.
// 16 warps/SM (2 CTAs). 3-stage cp.async, CP_WAIT(1), mid-chunk staging,
// warp de-phasing, one __syncthreads per chunk.
// biasMode: 0 none, 1 bias[col], 2 bias[row]. OUTMODE: 0 fp32 C, 1 fp16 C.
// A/B pointers pre-offset to the CTA tile.
// ---------------------------------------------------------------------------
template <int OUTMODE>
__device__ __forceinline__ void gemm_body(
    const __half* __restrict__ A, const __half* __restrict__ B,
    int lda, int ldb, int Kdim,
    const float* __restrict__ bias, int biasMode,
    float* __restrict__ C, __half* __restrict__ Ch,
    long long cbase, int ldc, int row0, int col0, float alpha)
{
    extern __shared__ char smem[];
    const uint32_t sb = smem_u32(smem);
    const int tid = threadIdx.x;
    const int lane = tid & 31;
    const int wid = tid >> 5;
    const int warpM = (wid & 1) * 64;
    const int warpN = (wid >> 1) * 32;
    const int khA = wid & 1;
    const int khB = khA ^ 1;

    float acc[4][4][4];
#pragma unroll
    for (int m = 0; m < 4; m++)
#pragma unroll
        for (int n = 0; n < 4; n++)
#pragma unroll
            for (int q = 0; q < 4; q++) acc[m][n][q] = 0.f;

    const int r0 = tid >> 2, q0 = tid & 3;
    const uint32_t so0 = (uint32_t)(r0 * 64 + ((q0 ^ ((r0 >> 1) & 3)) * 16));
    const __half* gA = A + (long long)r0 * lda + q0 * 8;
    const __half* gB = B + (long long)r0 * ldb + q0 * 8;
    const long long stepA = 64LL * lda;
    const long long stepB = 64LL * ldb;

    auto issueStage = [&](uint32_t st) {
#pragma unroll
        for (int p = 0; p < 2; p++) {
            const uint32_t so = so0 + (uint32_t)(p * 4096);
            cpa16(st + T_A + so, gA + p * stepA);
            cpa16(st + T_B + so, gB + p * stepB);
        }
        gA += 32; gB += 32;
        CP_COMMIT();
    };

    const int lr = lane & 15;
    const int lq = lane >> 4;
    const int lsw = (lr >> 1) & 3;
    const uint32_t rowA = (uint32_t)(warpM + lr);
    const uint32_t rowB = (uint32_t)(warpN + lr);

    // one kh half-chunk: 6 LDSM + 16 MMAs
    auto khPart = [&](uint32_t stb, int kh) {
        const uint32_t qb = (uint32_t)(((kh * 2 + lq) ^ lsw) * 16);
        uint32_t a[4][4], b[4][2];
#pragma unroll
        for (int mt = 0; mt < 4; mt++)
            ldsm4(a[mt], stb + T_A + (rowA + mt * 16) * 64 + qb);
#pragma unroll
        for (int np = 0; np < 2; np++) {
            uint32_t t[4];
            ldsm4(t, stb + T_B + (rowB + np * 16) * 64 + qb);
            b[2 * np][0] = t[0]; b[2 * np][1] = t[2];
            b[2 * np + 1][0] = t[1]; b[2 * np + 1][1] = t[3];
        }
#pragma unroll
        for (int mt = 0; mt < 4; mt++)
#pragma unroll
            for (int nt = 0; nt < 4; nt++) mma16816(acc[mt][nt], a[mt], b[nt]);
    };

    const int CH = Kdim >> 5;      // BK = 32
    const uint32_t sTop = sb + (NSTAGE - 1) * STAGE;
    uint32_t stW = sb, stR = sb;

    issueStage(stW); stW += STAGE;
    issueStage(stW); stW += STAGE;

    for (int c = 0; c < CH; c++) {
        if (c + 1 < CH) { CP_WAIT(1); } else { CP_WAIT(0); }
        __syncthreads();
        khPart(stR, khA);
        if (c + 2 < CH) {
            issueStage(stW);
            stW = (stW == sTop) ? sb : stW + STAGE;
        }
        khPart(stR, khB);
        stR = (stR == sTop) ? sb : stR + STAGE;
        // no tail sync: issue at iter c targets buffer (c-1)%3, which all
        // warps finished computing before this iteration's head sync.
    }

    // ---- epilogue ----
    const int g = lane >> 2, tg = lane & 3;
#pragma unroll
    for (int mt = 0; mt < 4; mt++) {
        const int row = row0 + warpM + mt * 16 + g;
        float rb0 = 0.f, rb8 = 0.f;
        if (biasMode == 2) { rb0 = bias[row]; rb8 = bias[row + 8]; }
#pragma unroll
        for (int nt = 0; nt < 4; nt++) {
            const int col = col0 + warpN + nt * 8 + tg * 2;
            float c0 = acc[mt][nt][0] * alpha;
            float c1 = acc[mt][nt][1] * alpha;
            float c2 = acc[mt][nt][2] * alpha;
            float c3 = acc[mt][nt][3] * alpha;
            if (biasMode == 1) {
                const float b0 = bias[col], b1 = bias[col + 1];
                c0 += b0; c1 += b1; c2 += b0; c3 += b1;
            } else if (biasMode == 2) {
                c0 += rb0; c1 += rb0; c2 += rb8; c3 += rb8;
            }
            const long long i0 = cbase + (long long)row * ldc + col;
            const long long i1 = i0 + (long long)8 * ldc;
            if (OUTMODE == 0) {
                *(float2*)(C + i0) = make_float2(c0, c1);
                *(float2*)(C + i1) = make_float2(c2, c3);
            } else {
                *(uint32_t*)(Ch + i0) = pack2h(c0, c1);
                *(uint32_t*)(Ch + i1) = pack2h(c2, c3);
            }
        }
    }
}

// ---------------------------------------------------------------------------
// Fused projection kernel: z=0 -> K, z=1 -> Q, z=2 -> Vt (remapped tiles).
// grid (8, 64, 3), 256 threads.
// ---------------------------------------------------------------------------
__global__ void __launch_bounds__(256, 2)
gemm_proj3(const __half* __restrict__ Xh, const __half* __restrict__ Wh,
           const float* __restrict__ bk, const float* __restrict__ bq,
           const float* __restrict__ bv,
           __half* __restrict__ Kh, __half* __restrict__ Qh,
           __half* __restrict__ Vth)
{
    const int WN = NE * NE;
    const int z = blockIdx.z;
    if (z < 2) {
        // K or Q = X @ W^T + b(col)
        const int row0 = blockIdx.y * 128;
        const int col0 = blockIdx.x * 128;
        const long long aoff = (long long)row0 * NE;
        const long long boff = (long long)z * WN + (long long)col0 * NE;
        gemm_body<1>(Xh + aoff, Wh + boff,
                     NE, NE, NE,
                     (z == 0) ? bk : bq, 1,
                     nullptr, (z == 0) ? Kh : Qh,
                     0, NE, row0, col0, 1.f);
    } else {
        // Vt = Wv @ X^T + bv(row)
        const int tx = blockIdx.x + (blockIdx.y & 7) * 8;  // 0..63 (N tiles)
        const int ty = blockIdx.y >> 3;                    // 0..7  (M tiles)
        const int row0 = ty * 128;
        const int col0 = tx * 128;
        const long long aoff = 2LL * WN + (long long)row0 * NE;
        const long long boff = (long long)col0 * NE;
        gemm_body<1>(Wh + aoff, Xh + boff,
                     NE, NE, NE,
                     bv, 2,
                     nullptr, Vth,
                     0, BSN, row0, col0, 1.f);
    }
}

// ---------------------------------------------------------------------------
// Plain batched NT GEMM wrapper (fp32 out, no bias).
// ---------------------------------------------------------------------------
__global__ void __launch_bounds__(256, 2)
gemm_nt(const __half* __restrict__ A, const __half* __restrict__ B,
        float* __restrict__ C,
        int lda, int ldb, int ldc, int Kdim,
        long long sA, long long sB, long long sC, float alpha)
{
    const int row0 = blockIdx.y * 128;
    const int col0 = blockIdx.x * 128;
    const long long aoff = (long long)blockIdx.z * sA + (long long)row0 * lda;
    const long long boff = (long long)blockIdx.z * sB + (long long)col0 * ldb;
    gemm_body<0>(A + aoff, B + boff,
                 lda, ldb, Kdim,
                 nullptr, 0,
                 C, nullptr,
                 (long long)blockIdx.z * sC, ldc, row0, col0, alpha);
}

// ---------------------------------------------------------------------------
// Fused fp32 -> fp16 convert over [X | Wk | Wq | Wv] (one launch).
// ---------------------------------------------------------------------------
#define X4  (BSN * NE / 4)
#define W4  (NE * NE / 4)
__global__ __launch_bounds__(256)
void cvtAll(const float* __restrict__ X,
            const float* __restrict__ Wk, const float* __restrict__ Wq,
            const float* __restrict__ Wv,
            __half* __restrict__ Xh, __half* __restrict__ Wh)
{
    const int i = blockIdx.x * 256 + threadIdx.x;
    const float* src;
    __half* dst;
    int j;
    if (i < X4)                { src = X;  dst = Xh;           j = i; }
    else if (i < X4 + W4)      { src = Wk; dst = Wh;           j = i - X4; }
    else if (i < X4 + 2 * W4)  { src = Wq; dst = Wh + NE*NE;   j = i - X4 - W4; }
    else                       { src = Wv; dst = Wh + 2*NE*NE; j = i - X4 - 2*W4; }
    const float4 v = ((const float4*)src)[j];
    ((uint2*)dst)[j] = make_uint2(pack2h(v.x, v.y), pack2h(v.z, v.w));
}

// ---------------------------------------------------------------------------
// Row softmax over 2048, emits fp16. One block (256 thr) per row.
// ---------------------------------------------------------------------------
__global__ __launch_bounds__(256)
void softmax2048(const float* __restrict__ P, __half* __restrict__ Ph)
{
    __shared__ float red[32];
    const float* p = P + (long long)blockIdx.x * NS;
    const int tid = threadIdx.x;

    float v[8];
    {
        const float4 a = *(const float4*)(p + tid * 8);
        const float4 b = *(const float4*)(p + tid * 8 + 4);
        v[0] = a.x; v[1] = a.y; v[2] = a.z; v[3] = a.w;
        v[4] = b.x; v[5] = b.y; v[6] = b.z; v[7] = b.w;
    }

    float m = v[0];
#pragma unroll
    for (int i = 1; i < 8; i++) m = fmaxf(m, v[i]);
#pragma unroll
    for (int o = 16; o > 0; o >>= 1) m = fmaxf(m, __shfl_xor_sync(0xffffffffu, m, o));
    if ((tid & 31) == 0) red[tid >> 5] = m;
    __syncthreads();
    if (tid < 32) {
        float t = (tid < 8) ? red[tid] : -INFINITY;
#pragma unroll
        for (int o = 4; o > 0; o >>= 1) t = fmaxf(t, __shfl_xor_sync(0xffffffffu, t, o));
        if (tid == 0) red[0] = t;
    }
    __syncthreads();
    m = red[0];
    __syncthreads();

    float s = 0.f;
#pragma unroll
    for (int i = 0; i < 8; i++) { v[i] = __expf(v[i] - m); s += v[i]; }
#pragma unroll
    for (int o = 16; o > 0; o >>= 1) s += __shfl_xor_sync(0xffffffffu, s, o);
    if ((tid & 31) == 0) red[tid >> 5] = s;
    __syncthreads();
    if (tid < 32) {
        float t = (tid < 8) ? red[tid] : 0.f;
#pragma unroll
        for (int o = 4; o > 0; o >>= 1) t += __shfl_xor_sync(0xffffffffu, t, o);
        if (tid == 0) red[0] = t;
    }
    __syncthreads();
    const float inv = 1.f / red[0];

    uint4 H;
    H.x = pack2h(v[0] * inv, v[1] * inv);
    H.y = pack2h(v[2] * inv, v[3] * inv);
    H.z = pack2h(v[4] * inv, v[5] * inv);
    H.w = pack2h(v[6] * inv, v[7] * inv);
    const long long o = (long long)blockIdx.x * NS + tid * 8;
    *(uint4*)(Ph + o) = H;
}

// ---------------------------------------------------------------------------
// Launcher.
// ---------------------------------------------------------------------------
extern "C" void kernel_launch(void* const* d_in, const int* in_sizes, int n_in,
                              void* d_out, int out_size)
{
    const float* X  = (const float*)d_in[0];
    const float* Wk = (const float*)d_in[1];
    const float* bk = (const float*)d_in[2];
    const float* Wq = (const float*)d_in[3];
    const float* bq = (const float*)d_in[4];
    const float* Wv = (const float*)d_in[5];
    const float* bv = (const float*)d_in[6];
    float* Y = (float*)d_out;

    __half *Xh, *Wh, *Qh, *Kh, *Vth, *Ph;
    float* Pp;
    cudaGetSymbolAddress((void**)&Xh, g_Xh);
    cudaGetSymbolAddress((void**)&Wh, g_Wh);
    cudaGetSymbolAddress((void**)&Qh, g_Qh);
    cudaGetSymbolAddress((void**)&Kh, g_Kh);
    cudaGetSymbolAddress((void**)&Vth, g_Vth);
    cudaGetSymbolAddress((void**)&Ph, g_Ph);
    cudaGetSymbolAddress((void**)&Pp, g_P);

    cudaFuncSetAttribute(gemm_proj3, cudaFuncAttributeMaxDynamicSharedMemorySize, SMEM_TOTAL);
    cudaFuncSetAttribute(gemm_nt,    cudaFuncAttributeMaxDynamicSharedMemorySize, SMEM_TOTAL);

    const dim3 blk(256);

    // one fused convert launch: X, Wk, Wq, Wv -> fp16
    cvtAll<<<(X4 + 3 * W4) / 256, 256>>>(X, Wk, Wq, Wv, Xh, Wh);

    // All three projections in ONE launch (z=0 K, z=1 Q, z=2 Vt)
    {
        dim3 grid(NE / 128, BSN / 128, 3);
        gemm_proj3<<<grid, blk, SMEM_TOTAL>>>(Xh, Wh, bk, bq, bv, Kh, Qh, Vth);
    }
    // Scores: P[b,j,i] = Q_j . K_i / sqrt(S)
    {
        dim3 grid(NS / 128, NS / 128, NB);
        const float alpha = rsqrtf((float)NS);
        gemm_nt<<<grid, blk, SMEM_TOTAL>>>(
            Qh, Kh, Pp,
            NE, NE, NS, NE,
            (long long)NS * NE, (long long)NS * NE, (long long)NS * NS, alpha);
    }
    // Softmax over key index i -> fp16
    softmax2048<<<NB * NS, 256>>>(Pp, Ph);

    // Y = P @ Vt^T
    {
        dim3 grid(NE / 128, NS / 128, NB);
        gemm_nt<<<grid, blk, SMEM_TOTAL>>>(
            Ph, Vth, Y,
            NS, BSN, NE, NS,
            (long long)NS * NS, (long long)NS, (long long)NS * NE, 1.f);
    }
}